// round 2
// baseline (speedup 1.0000x reference)
#include <cuda_runtime.h>

#define FULLMASK 0xffffffffu
#define NMAX 100000

// scatter-mean scratch (no allocations allowed -> __device__ globals)
static __device__ float g_sum_i[NMAX];
static __device__ float g_sum_j[NMAX];
static __device__ float g_cnt_i[NMAX];
static __device__ float g_cnt_j[NMAX];

// ---- f32x2 packed-FMA helpers (sm_103a; ptxas never auto-fuses these) ----
__device__ __forceinline__ unsigned long long pk2(float lo, float hi) {
    unsigned long long r;
    asm("mov.b64 %0, {%1, %2};" : "=l"(r) : "f"(lo), "f"(hi));
    return r;
}
__device__ __forceinline__ void upk2(unsigned long long v, float& lo, float& hi) {
    asm("mov.b64 {%0, %1}, %2;" : "=f"(lo), "=f"(hi) : "l"(v));
}
__device__ __forceinline__ void ffma2(unsigned long long& d,
                                      unsigned long long a,
                                      unsigned long long b) {
    asm("fma.rn.f32x2 %0, %1, %2, %0;" : "+l"(d) : "l"(a), "l"(b));
}

__device__ __forceinline__ float silu_f(float z) {
    // z * sigmoid(z); __expf/__fdividef rel err ~2^-21, far under 1e-3 budget
    return __fdividef(z, 1.0f + __expf(-z));
}

__global__ void zero_kernel(int n) {
    int t = blockIdx.x * blockDim.x + threadIdx.x;
    if (t < n) {
        g_sum_i[t] = 0.f; g_sum_j[t] = 0.f;
        g_cnt_i[t] = 0.f; g_cnt_j[t] = 0.f;
    }
}

__global__ void count_kernel(const int* __restrict__ e0,
                             const int* __restrict__ e1, int E) {
    int t = blockIdx.x * blockDim.x + threadIdx.x;
    int stride = gridDim.x * blockDim.x;
    for (int e = t; e < E; e += stride) {
        atomicAdd(&g_cnt_i[e0[e]], 1.f);
        atomicAdd(&g_cnt_j[e1[e]], 1.f);
    }
}

__global__ void finalize_kernel(float* __restrict__ out, int n) {
    int t = blockIdx.x * blockDim.x + threadIdx.x;
    if (t < n) {
        out[t] = g_sum_i[t] / fmaxf(g_cnt_i[t], 1.f)
               + g_sum_j[t] / fmaxf(g_cnt_j[t], 1.f);
    }
}

// Fused edge MLP: each warp handles 4 edges x 2 directions = 8 rows.
// Lane owns hidden units [4*lane .. 4*lane+3]. W1 transposed in dyn SMEM:
// W1ts[c*128 + u] = W1[u][c], so the inner product reads one conflict-free
// LDS.128 per k-step shared by all 8 rows.
__global__ void __launch_bounds__(256)
edge_kernel(const float* __restrict__ v,
            const float* __restrict__ r_ij,
            const float* __restrict__ W0,
            const float* __restrict__ b0,
            const float* __restrict__ W1,
            const float* __restrict__ b1,
            const float* __restrict__ W2,
            const float* __restrict__ b2,
            const int* __restrict__ ei0,
            const int* __restrict__ ei1,
            int E) {
    extern __shared__ __align__(16) float W1ts[];  // 128*128 floats = 64KB, transposed
    __shared__ float W0s[512], b0s[128], b1s[128], W2s[128];

    const int tid = threadIdx.x;
    for (int idx = tid; idx < 128 * 128; idx += blockDim.x) {
        int u = idx >> 7, c = idx & 127;
        W1ts[c * 128 + u] = W1[idx];
    }
    for (int idx = tid; idx < 512; idx += blockDim.x) W0s[idx] = W0[idx];
    if (tid < 128) { b0s[tid] = b0[tid]; b1s[tid] = b1[tid]; W2s[tid] = W2[tid]; }
    __syncthreads();

    const int lane  = tid & 31;
    const int warp  = tid >> 5;
    const int gwarp = blockIdx.x * (blockDim.x >> 5) + warp;
    const int nwarp = gridDim.x * (blockDim.x >> 5);
    const int ntask = (E + 3) >> 2;
    const float b2v = b2[0];

    // per-lane W2 slice + b1 pair inits (loop-invariant)
    const float w2a = W2s[4 * lane], w2b = W2s[4 * lane + 1];
    const float w2c = W2s[4 * lane + 2], w2d = W2s[4 * lane + 3];
    const unsigned long long binit0 = pk2(b1s[4 * lane],     b1s[4 * lane + 1]);
    const unsigned long long binit1 = pk2(b1s[4 * lane + 2], b1s[4 * lane + 3]);
    const float4* wrowbase = reinterpret_cast<const float4*>(W1ts) + lane;

    for (int task = gwarp; task < ntask; task += nwarp) {
        const int e0 = task << 2;
        int ii[4], jj[4];
        float rr[4], vx[4], vy[4], vz[4];
#pragma unroll
        for (int k = 0; k < 4; k++) {
            int e = min(e0 + k, E - 1);   // clamp tail; atomics guarded below
            ii[k] = ei0[e];
            jj[k] = ei1[e];
            float a0 = r_ij[3 * e], a1 = r_ij[3 * e + 1], a2 = r_ij[3 * e + 2];
            rr[k] = sqrtf(a0 * a0 + a1 * a1 + a2 * a2) * (1.0f / 3.0f);  // /H, H=3
            vx[k] = v[3 * ii[k]]     - v[3 * jj[k]];
            vy[k] = v[3 * ii[k] + 1] - v[3 * jj[k] + 1];
            vz[k] = v[3 * ii[k] + 2] - v[3 * jj[k] + 2];
        }

        // Layer 0: rows 2k (dir i, +v) and 2k+1 (dir j, -v) share the r-term
        float h1v[8][4];
#pragma unroll
        for (int q = 0; q < 4; q++) {
            int u = 4 * lane + q;
            float w0a = W0s[4 * u], w0b = W0s[4 * u + 1];
            float w0c = W0s[4 * u + 2], w0d = W0s[4 * u + 3];
            float bb = b0s[u];
#pragma unroll
            for (int k = 0; k < 4; k++) {
                float tr = fmaf(w0a, rr[k], bb);
                float tv = w0b * vx[k] + w0c * vy[k] + w0d * vz[k];
                h1v[2 * k][q]     = silu_f(tr + tv);
                h1v[2 * k + 1][q] = silu_f(tr - tv);
            }
        }

        // Layer 1: 128x128 inner products, f32x2 packed accumulation
        unsigned long long acc[8][2];
#pragma unroll
        for (int r = 0; r < 8; r++) { acc[r][0] = binit0; acc[r][1] = binit1; }

#pragma unroll 4
        for (int cq = 0; cq < 32; ++cq) {
#pragma unroll
            for (int el = 0; el < 4; ++el) {
                int c = 4 * cq + el;               // owner lane = cq, reg = el
                float4 w = wrowbase[c * 32];        // W1t[c][4*lane .. +3]
                unsigned long long wlo = pk2(w.x, w.y);
                unsigned long long whi = pk2(w.z, w.w);
#pragma unroll
                for (int r = 0; r < 8; r++) {
                    float hv = __shfl_sync(FULLMASK, h1v[r][el], cq);
                    unsigned long long hh = pk2(hv, hv);
                    ffma2(acc[r][0], hh, wlo);
                    ffma2(acc[r][1], hh, whi);
                }
            }
        }

        // Layer 2 (dot with W2) + warp reduce + scatter atomics
#pragma unroll
        for (int r = 0; r < 8; r++) {
            float z0, z1, z2, z3;
            upk2(acc[r][0], z0, z1);
            upk2(acc[r][1], z2, z3);
            float p = silu_f(z0) * w2a + silu_f(z1) * w2b
                    + silu_f(z2) * w2c + silu_f(z3) * w2d;
            p += __shfl_xor_sync(FULLMASK, p, 16);
            p += __shfl_xor_sync(FULLMASK, p, 8);
            p += __shfl_xor_sync(FULLMASK, p, 4);
            p += __shfl_xor_sync(FULLMASK, p, 2);
            p += __shfl_xor_sync(FULLMASK, p, 1);
            if (lane == r) {
                int k = r >> 1;
                if (e0 + k < E) {
                    float m = p + b2v;
                    if ((r & 1) == 0) atomicAdd(&g_sum_i[ii[k]], m);
                    else              atomicAdd(&g_sum_j[jj[k]], m);
                }
            }
        }
    }
}

extern "C" void kernel_launch(void* const* d_in, const int* in_sizes, int n_in,
                              void* d_out, int out_size) {
    const float* v   = (const float*)d_in[0];
    const float* rij = (const float*)d_in[1];
    const float* W0  = (const float*)d_in[2];
    const float* b0  = (const float*)d_in[3];
    const float* W1  = (const float*)d_in[4];
    const float* b1  = (const float*)d_in[5];
    const float* W2  = (const float*)d_in[6];
    const float* b2  = (const float*)d_in[7];
    const int*   ei  = (const int*)d_in[8];     // edge_index is int32 on device (JAX x64 disabled)

    const int E = in_sizes[8] / 2;      // edge_index is [2,E]
    const int N = out_size;             // 100000
    float* out = (float*)d_out;

    cudaFuncSetAttribute(edge_kernel,
                         cudaFuncAttributeMaxDynamicSharedMemorySize, 65536);

    int nb = (N + 255) / 256;
    zero_kernel<<<nb, 256>>>(N);
    count_kernel<<<2048, 256>>>(ei, ei + E, E);
    edge_kernel<<<888, 256, 65536>>>(v, rij, W0, b0, W1, b1, W2, b2,
                                     ei, ei + E, E);
    finalize_kernel<<<nb, 256>>>(out, N);
}

// round 4
// speedup vs baseline: 3.1878x; 3.1878x over previous
#include <cuda_runtime.h>
#include <cstdint>

#define FULLMASK 0xffffffffu
#define NMAX 100000
#define BPITCH 136   // floats; 136 mod 32 = 8 -> B-frag banks 8m+q, conflict-free

static __device__ float g_sum_i[NMAX];
static __device__ float g_sum_j[NMAX];
static __device__ float g_cnt_i[NMAX];
static __device__ float g_cnt_j[NMAX];

__device__ __forceinline__ uint32_t to_tf32(float f) {
    uint32_t r;
    asm("cvt.rna.tf32.f32 %0, %1;" : "=r"(r) : "f"(f));
    return r;
}
__device__ __forceinline__ float silu_f(float z) {
    return __fdividef(z, 1.0f + __expf(-z));   // 2 MUFU, rel err ~2^-21
}
__device__ __forceinline__ void mma_tf32(float* d, const uint32_t* a,
                                         uint32_t b0, uint32_t b1) {
    asm volatile(
        "mma.sync.aligned.m16n8k8.row.col.f32.tf32.tf32.f32 "
        "{%0,%1,%2,%3}, {%4,%5,%6,%7}, {%8,%9}, {%0,%1,%2,%3};"
        : "+f"(d[0]), "+f"(d[1]), "+f"(d[2]), "+f"(d[3])
        : "r"(a[0]), "r"(a[1]), "r"(a[2]), "r"(a[3]), "r"(b0), "r"(b1));
}

__global__ void zero_kernel(int n) {
    int t = blockIdx.x * blockDim.x + threadIdx.x;
    if (t < n) {
        g_sum_i[t] = 0.f; g_sum_j[t] = 0.f;
        g_cnt_i[t] = 0.f; g_cnt_j[t] = 0.f;
    }
}
__global__ void finalize_kernel(float* __restrict__ out, int n) {
    int t = blockIdx.x * blockDim.x + threadIdx.x;
    if (t < n) {
        out[t] = g_sum_i[t] / fmaxf(g_cnt_i[t], 1.f)
               + g_sum_j[t] / fmaxf(g_cnt_j[t], 1.f);
    }
}

// Each warp-task: 8 edges x 2 directions = one m16 row tile, n=128, k=128.
// Layer0 -> A frags in regs; layer1 via mma.sync tf32; epilogue fused.
__global__ void __launch_bounds__(256, 1)
edge_kernel(const float* __restrict__ v,
            const float* __restrict__ r_ij,
            const float* __restrict__ W0,
            const float* __restrict__ b0,
            const float* __restrict__ W1,
            const float* __restrict__ b1,
            const float* __restrict__ W2,
            const float* __restrict__ b2,
            const int* __restrict__ ei0,
            const int* __restrict__ ei1,
            int E) {
    extern __shared__ float Bs[];            // [128][BPITCH] = W1^T as tf32
    __shared__ float4 W0s4[128];
    __shared__ float  b0s[128];
    __shared__ float2 s_bw[128];             // (b1, W2) interleaved

    const int tid = threadIdx.x;

    // one-time weight staging
    for (int idx = tid; idx < 128 * 128; idx += 256) {
        int k = idx & 127, n = idx >> 7;
        Bs[k * BPITCH + n] = __uint_as_float(to_tf32(W1[n * 128 + k]));
    }
    if (tid < 128) {
        W0s4[tid] = ((const float4*)W0)[tid];
        b0s[tid]  = b0[tid];
        s_bw[tid] = make_float2(b1[tid], W2[tid]);
    }
    __syncthreads();

    const int lane = tid & 31;
    const int m    = lane & 3;    // thread-in-group (frag col sel)
    const int q    = lane >> 2;   // group id = tile row 0..7 (row q and q+8)
    const int el0  = lane >> 3;   // edge slot of row q (0..3); row q+8 -> el0+4
    const int dir  = q & 1;       // 0: i-direction (+v), 1: j-direction (-v)
    const float sgn = dir ? -1.f : 1.f;
    const float b2v = b2[0];

    const int gw = (blockIdx.x << 3) + (tid >> 5);
    const int nw = gridDim.x << 3;
    const int ntask = (E + 7) >> 3;

    for (int task = gw; task < ntask; task += nw) {
        const int base = task << 3;

        // lanes 0-7: gather edge data + fused count scatter
        int ii = 0, jj = 0;
        float rr = 0.f, dx = 0.f, dy = 0.f, dz = 0.f;
        if (lane < 8) {
            int e = base + lane;
            bool valid = e < E;
            int ec = valid ? e : E - 1;
            ii = ei0[ec]; jj = ei1[ec];
            float a0 = r_ij[3 * ec], a1 = r_ij[3 * ec + 1], a2 = r_ij[3 * ec + 2];
            rr = sqrtf(a0 * a0 + a1 * a1 + a2 * a2) * (1.0f / 3.0f);  // /H, H=3
            dx = v[3 * ii]     - v[3 * jj];
            dy = v[3 * ii + 1] - v[3 * jj + 1];
            dz = v[3 * ii + 2] - v[3 * jj + 2];
            if (valid) {
                atomicAdd(&g_cnt_i[ii], 1.f);
                atomicAdd(&g_cnt_j[jj], 1.f);
            }
        }
        // broadcast per-row inputs (row q -> edge el0, row q+8 -> edge el0+4)
        float rr0 = __shfl_sync(FULLMASK, rr, el0);
        float vx0 = __shfl_sync(FULLMASK, dx, el0) * sgn;
        float vy0 = __shfl_sync(FULLMASK, dy, el0) * sgn;
        float vz0 = __shfl_sync(FULLMASK, dz, el0) * sgn;
        float rr1 = __shfl_sync(FULLMASK, rr, el0 + 4);
        float vx1 = __shfl_sync(FULLMASK, dx, el0 + 4) * sgn;
        float vy1 = __shfl_sync(FULLMASK, dy, el0 + 4) * sgn;
        float vz1 = __shfl_sync(FULLMASK, dz, el0 + 4) * sgn;
        int ii0 = __shfl_sync(FULLMASK, ii, el0);
        int jj0 = __shfl_sync(FULLMASK, jj, el0);
        int ii1 = __shfl_sync(FULLMASK, ii, el0 + 4);
        int jj1 = __shfl_sync(FULLMASK, jj, el0 + 4);

        // ---- layer 0 directly into A-fragment registers ----
        // a[4k+0]: (row q,   col 8k+m)   a[4k+1]: (row q+8, col 8k+m)
        // a[4k+2]: (row q,   col 8k+m+4) a[4k+3]: (row q+8, col 8k+m+4)
        uint32_t afrag[64];
#pragma unroll
        for (int t = 0; t < 32; t++) {
            int c = 4 * t + m;
            float4 w = W0s4[c];
            float bb = b0s[c];
            float z0 = fmaf(w.x, rr0, bb) + fmaf(w.y, vx0, fmaf(w.z, vy0, w.w * vz0));
            float z1 = fmaf(w.x, rr1, bb) + fmaf(w.y, vx1, fmaf(w.z, vy1, w.w * vz1));
            int k = t >> 1, h = t & 1;
            afrag[4 * k + 2 * h]     = to_tf32(silu_f(z0));
            afrag[4 * k + 2 * h + 1] = to_tf32(silu_f(z1));
        }

        // ---- layer 1: D(16x128) = A(16x128) @ W1^T via 16x16 mma.sync ----
        float acc[16][4];
#pragma unroll
        for (int n = 0; n < 16; n++)
            acc[n][0] = acc[n][1] = acc[n][2] = acc[n][3] = 0.f;
#pragma unroll
        for (int k = 0; k < 16; k++) {
            const float* bp = Bs + (8 * k + m) * BPITCH + q;
#pragma unroll
            for (int n = 0; n < 16; n++) {
                uint32_t bb0 = __float_as_uint(bp[8 * n]);
                uint32_t bb1 = __float_as_uint(bp[8 * n + 4 * BPITCH]);
                mma_tf32(acc[n], &afrag[4 * k], bb0, bb1);
            }
        }

        // ---- epilogue: sum_c silu(h2+b1[c])*W2[c], quad-reduce, scatter ----
        float p0 = 0.f, p1 = 0.f;
#pragma unroll
        for (int n = 0; n < 16; n++) {
            int c0 = 8 * n + 2 * m;
            float2 bw0 = s_bw[c0];
            float2 bw1 = s_bw[c0 + 1];
            p0 += silu_f(acc[n][0] + bw0.x) * bw0.y
                + silu_f(acc[n][1] + bw1.x) * bw1.y;
            p1 += silu_f(acc[n][2] + bw0.x) * bw0.y
                + silu_f(acc[n][3] + bw1.x) * bw1.y;
        }
        p0 += __shfl_xor_sync(FULLMASK, p0, 1);
        p0 += __shfl_xor_sync(FULLMASK, p0, 2);
        p1 += __shfl_xor_sync(FULLMASK, p1, 1);
        p1 += __shfl_xor_sync(FULLMASK, p1, 2);
        if (m == 0) {
            if (base + el0 < E) {
                float val = p0 + b2v;
                if (dir == 0) atomicAdd(&g_sum_i[ii0], val);
                else          atomicAdd(&g_sum_j[jj0], val);
            }
            if (base + el0 + 4 < E) {
                float val = p1 + b2v;
                if (dir == 0) atomicAdd(&g_sum_i[ii1], val);
                else          atomicAdd(&g_sum_j[jj1], val);
            }
        }
    }
}

extern "C" void kernel_launch(void* const* d_in, const int* in_sizes, int n_in,
                              void* d_out, int out_size) {
    const float* v   = (const float*)d_in[0];
    const float* rij = (const float*)d_in[1];
    const float* W0  = (const float*)d_in[2];
    const float* b0  = (const float*)d_in[3];
    const float* W1  = (const float*)d_in[4];
    const float* b1  = (const float*)d_in[5];
    const float* W2  = (const float*)d_in[6];
    const float* b2  = (const float*)d_in[7];
    const int*   ei  = (const int*)d_in[8];   // int32 on device (JAX x64 off)

    const int E = in_sizes[8] / 2;            // edge_index is [2,E]
    const int N = out_size;
    float* out = (float*)d_out;

    const int DSMEM = 128 * BPITCH * 4;       // 69632 B
    cudaFuncSetAttribute(edge_kernel,
                         cudaFuncAttributeMaxDynamicSharedMemorySize, DSMEM);

    int nb = (N + 255) / 256;
    zero_kernel<<<nb, 256>>>(N);
    edge_kernel<<<148, 256, DSMEM>>>(v, rij, W0, b0, W1, b1, W2, b2,
                                     ei, ei + E, E);
    finalize_kernel<<<nb, 256>>>(out, N);
}

// round 5
// speedup vs baseline: 3.9891x; 1.2514x over previous
#include <cuda_runtime.h>
#include <cstdint>

#define FULLMASK 0xffffffffu
#define NMAX 100000
#define BP2 132   // float2 pitch: 4m+q mod 16 uniform 2-way -> optimal 2-phase LDS.64

static __device__ float g_sum_i[NMAX];
static __device__ float g_sum_j[NMAX];
static __device__ float g_cnt_i[NMAX];
static __device__ float g_cnt_j[NMAX];

__device__ __forceinline__ uint32_t to_tf32(float f) {
    uint32_t r;
    asm("cvt.rna.tf32.f32 %0, %1;" : "=r"(r) : "f"(f));
    return r;
}
__device__ __forceinline__ float silu_t(float z) {
    float zh = 0.5f * z, t;
    asm("tanh.approx.f32 %0, %1;" : "=f"(t) : "f"(zh));
    return fmaf(zh, t, zh);   // z*sigmoid(z) = zh*(1+tanh(zh)); 1 MUFU
}
__device__ __forceinline__ void mma_tf32(float* d, const uint32_t* a,
                                         uint32_t b0, uint32_t b1) {
    asm volatile(
        "mma.sync.aligned.m16n8k8.row.col.f32.tf32.tf32.f32 "
        "{%0,%1,%2,%3}, {%4,%5,%6,%7}, {%8,%9}, {%0,%1,%2,%3};"
        : "+f"(d[0]), "+f"(d[1]), "+f"(d[2]), "+f"(d[3])
        : "r"(a[0]), "r"(a[1]), "r"(a[2]), "r"(a[3]), "r"(b0), "r"(b1));
}

__global__ void zero_kernel(int n) {
    int t = blockIdx.x * blockDim.x + threadIdx.x;
    if (t < n) {
        g_sum_i[t] = 0.f; g_sum_j[t] = 0.f;
        g_cnt_i[t] = 0.f; g_cnt_j[t] = 0.f;
    }
}
__global__ void finalize_kernel(float* __restrict__ out, int n) {
    int t = blockIdx.x * blockDim.x + threadIdx.x;
    if (t < n) {
        out[t] = g_sum_i[t] / fmaxf(g_cnt_i[t], 1.f)
               + g_sum_j[t] / fmaxf(g_cnt_j[t], 1.f);
    }
}

// Warp-task: 16 edges x 2 dirs = two m16 tiles; n=128, k=128 via mma.sync tf32.
// B packed as float2 (rows k, k+4) so one LDS.64 feeds both b-frag regs and
// each load is reused by both m-tiles.
__global__ void __launch_bounds__(256, 1)
edge_kernel(const float* __restrict__ v,
            const float* __restrict__ r_ij,
            const float* __restrict__ W0,
            const float* __restrict__ b0,
            const float* __restrict__ W1,
            const float* __restrict__ b1,
            const float* __restrict__ W2,
            const float* __restrict__ b2,
            const int* __restrict__ ei0,
            const int* __restrict__ ei1,
            int E) {
    extern __shared__ float2 Bp[];           // [64][BP2]: (W1T[8k+m][n], W1T[8k+m+4][n])
    __shared__ float4 W0s4[128];
    __shared__ float  b0s[128];
    __shared__ float2 s_bw[128];             // (b1, W2)

    const int tid = threadIdx.x;

    for (int idx = tid; idx < 64 * 128; idx += 256) {
        int k4 = idx >> 7, n = idx & 127;
        int krow = ((k4 >> 2) << 3) + (k4 & 3);
        Bp[k4 * BP2 + n] = make_float2(
            __uint_as_float(to_tf32(W1[n * 128 + krow])),
            __uint_as_float(to_tf32(W1[n * 128 + krow + 4])));
    }
    if (tid < 128) {
        W0s4[tid] = ((const float4*)W0)[tid];
        b0s[tid]  = b0[tid];
        s_bw[tid] = make_float2(b1[tid], W2[tid]);
    }
    __syncthreads();

    const int lane = tid & 31;
    const int m    = lane & 3;    // frag col group
    const int q    = lane >> 2;   // frag row group (rows q, q+8)
    const int el0  = lane >> 3;   // edge slot of row q within a tile (q>>1)
    const int dir  = q & 1;       // row = 2*edge + dir
    const float sgn = dir ? -1.f : 1.f;
    const float b2v = b2[0];

    const int gw = (blockIdx.x << 3) + (tid >> 5);
    const int nw = gridDim.x << 3;
    const int ntask = (E + 15) >> 4;

    for (int task = gw; task < ntask; task += nw) {
        const int base = task << 4;

        // lanes 0-15 gather 16 edges + fused count scatter
        int ii = 0, jj = 0;
        float rr = 0.f, dx = 0.f, dy = 0.f, dz = 0.f;
        if (lane < 16) {
            int e = base + lane;
            bool valid = e < E;
            int ec = valid ? e : E - 1;
            ii = ei0[ec]; jj = ei1[ec];
            float a0 = r_ij[3 * ec], a1 = r_ij[3 * ec + 1], a2 = r_ij[3 * ec + 2];
            rr = sqrtf(a0 * a0 + a1 * a1 + a2 * a2) * (1.0f / 3.0f);   // /H, H=3
            dx = v[3 * ii]     - v[3 * jj];
            dy = v[3 * ii + 1] - v[3 * jj + 1];
            dz = v[3 * ii + 2] - v[3 * jj + 2];
            if (valid) {
                atomicAdd(&g_cnt_i[ii], 1.f);
                atomicAdd(&g_cnt_j[jj], 1.f);
            }
        }
        // broadcasts: s = 2*tile + half; source edge slot = 8*tile + 4*half + el0
        float rrb[4], vxb[4], vyb[4], vzb[4];
        int iib[4], jjb[4];
#pragma unroll
        for (int s = 0; s < 4; s++) {
            int src = ((s >> 1) << 3) + ((s & 1) << 2) + el0;
            rrb[s] = __shfl_sync(FULLMASK, rr, src);
            vxb[s] = __shfl_sync(FULLMASK, dx, src) * sgn;
            vyb[s] = __shfl_sync(FULLMASK, dy, src) * sgn;
            vzb[s] = __shfl_sync(FULLMASK, dz, src) * sgn;
            iib[s] = __shfl_sync(FULLMASK, ii, src);
            jjb[s] = __shfl_sync(FULLMASK, jj, src);
        }

        float acc[32][4];
#pragma unroll
        for (int n = 0; n < 32; n++)
            acc[n][0] = acc[n][1] = acc[n][2] = acc[n][3] = 0.f;

#pragma unroll
        for (int k = 0; k < 16; k++) {
            // layer 0 -> A frags for this k-step (cols 8k+m, 8k+m+4)
            uint32_t af0[4], af1[4];
#pragma unroll
            for (int h = 0; h < 2; h++) {
                int c = 8 * k + m + 4 * h;
                float4 w = W0s4[c];
                float bb = b0s[c];
#pragma unroll
                for (int s = 0; s < 4; s++) {   // s = 2*tile + rowhalf
                    float z = fmaf(w.x, rrb[s], bb)
                            + fmaf(w.y, vxb[s], fmaf(w.z, vyb[s], w.w * vzb[s]));
                    uint32_t val = to_tf32(silu_t(z));
                    if (s < 2) af0[2 * h + s] = val;
                    else       af1[2 * h + (s - 2)] = val;
                }
            }
            const float2* bp = Bp + (k * 4 + m) * BP2 + q;
#pragma unroll
            for (int n = 0; n < 16; n++) {
                float2 b = bp[8 * n];
                uint32_t bb0 = __float_as_uint(b.x);
                uint32_t bb1 = __float_as_uint(b.y);
                mma_tf32(acc[n],      af0, bb0, bb1);
                mma_tf32(acc[16 + n], af1, bb0, bb1);
            }
        }

        // epilogue per tile: sum_c silu(h2+b1)*W2, quad-reduce, scatter
#pragma unroll
        for (int t = 0; t < 2; t++) {
            float p0 = 0.f, p1 = 0.f;
#pragma unroll
            for (int n = 0; n < 16; n++) {
                int c0 = 8 * n + 2 * m;
                float2 bw0 = s_bw[c0];
                float2 bw1 = s_bw[c0 + 1];
                const float* a = acc[16 * t + n];
                p0 += silu_t(a[0] + bw0.x) * bw0.y + silu_t(a[1] + bw1.x) * bw1.y;
                p1 += silu_t(a[2] + bw0.x) * bw0.y + silu_t(a[3] + bw1.x) * bw1.y;
            }
            p0 += __shfl_xor_sync(FULLMASK, p0, 1);
            p0 += __shfl_xor_sync(FULLMASK, p0, 2);
            p1 += __shfl_xor_sync(FULLMASK, p1, 1);
            p1 += __shfl_xor_sync(FULLMASK, p1, 2);
            if (m == 0) {
                int s0 = 2 * t, s1 = 2 * t + 1;
                int e0 = base + 8 * t + el0;
                if (e0 < E) {
                    float val = p0 + b2v;
                    if (dir == 0) atomicAdd(&g_sum_i[iib[s0]], val);
                    else          atomicAdd(&g_sum_j[jjb[s0]], val);
                }
                if (e0 + 4 < E) {
                    float val = p1 + b2v;
                    if (dir == 0) atomicAdd(&g_sum_i[iib[s1]], val);
                    else          atomicAdd(&g_sum_j[jjb[s1]], val);
                }
            }
        }
    }
}

extern "C" void kernel_launch(void* const* d_in, const int* in_sizes, int n_in,
                              void* d_out, int out_size) {
    const float* v   = (const float*)d_in[0];
    const float* rij = (const float*)d_in[1];
    const float* W0  = (const float*)d_in[2];
    const float* b0  = (const float*)d_in[3];
    const float* W1  = (const float*)d_in[4];
    const float* b1  = (const float*)d_in[5];
    const float* W2  = (const float*)d_in[6];
    const float* b2  = (const float*)d_in[7];
    const int*   ei  = (const int*)d_in[8];   // int32 on device (JAX x64 off)

    const int E = in_sizes[8] / 2;            // edge_index is [2,E]
    const int N = out_size;
    float* out = (float*)d_out;

    const int DSMEM = 64 * BP2 * 8;           // 67584 B
    cudaFuncSetAttribute(edge_kernel,
                         cudaFuncAttributeMaxDynamicSharedMemorySize, DSMEM);

    int nb = (N + 255) / 256;
    zero_kernel<<<nb, 256>>>(N);
    edge_kernel<<<148, 256, DSMEM>>>(v, rij, W0, b0, W1, b1, W2, b2,
                                     ei, ei + E, E);
    finalize_kernel<<<nb, 256>>>(out, N);
}

// round 6
// speedup vs baseline: 4.0633x; 1.0186x over previous
#include <cuda_runtime.h>
#include <cstdint>

#define FULLMASK 0xffffffffu
#define NMAX 100000
#define BP4 130   // float4 pitch; 130 mod 8 = 2 -> 8-lane phases hit distinct 16B banks

static __device__ float g_sum_i[NMAX];
static __device__ float g_sum_j[NMAX];
static __device__ float g_cnt_i[NMAX];
static __device__ float g_cnt_j[NMAX];

__device__ __forceinline__ uint32_t to_tf32(float f) {
    uint32_t r;
    asm("cvt.rna.tf32.f32 %0, %1;" : "=r"(r) : "f"(f));
    return r;
}
__device__ __forceinline__ float silu_t(float z) {
    float zh = 0.5f * z, t;
    asm("tanh.approx.f32 %0, %1;" : "=f"(t) : "f"(zh));
    return fmaf(zh, t, zh);   // z*sigmoid(z) = zh*(1+tanh(zh)); 1 MUFU
}
__device__ __forceinline__ void mma_tf32(float* d, const uint32_t* a,
                                         uint32_t b0, uint32_t b1) {
    asm volatile(
        "mma.sync.aligned.m16n8k8.row.col.f32.tf32.tf32.f32 "
        "{%0,%1,%2,%3}, {%4,%5,%6,%7}, {%8,%9}, {%0,%1,%2,%3};"
        : "+f"(d[0]), "+f"(d[1]), "+f"(d[2]), "+f"(d[3])
        : "r"(a[0]), "r"(a[1]), "r"(a[2]), "r"(a[3]), "r"(b0), "r"(b1));
}

__global__ void zero_kernel(int n) {
    int t = blockIdx.x * blockDim.x + threadIdx.x;
    if (t < n) {
        g_sum_i[t] = 0.f; g_sum_j[t] = 0.f;
        g_cnt_i[t] = 0.f; g_cnt_j[t] = 0.f;
    }
}
__global__ void dummy_kernel() {}   // launch-slot padding so ncu (#4) hits edge_kernel
__global__ void finalize_kernel(float* __restrict__ out, int n) {
    int t = blockIdx.x * blockDim.x + threadIdx.x;
    if (t < n) {
        out[t] = g_sum_i[t] / fmaxf(g_cnt_i[t], 1.f)
               + g_sum_j[t] / fmaxf(g_cnt_j[t], 1.f);
    }
}

// Warp-task: 16 edges x 2 dirs = two m16 tiles; n=128, k=128 via mma.sync tf32.
// B packed as float4 spanning TWO k-steps: rows (8k+m, 8k+m+4, 8k+8+m, 8k+12+m).
__global__ void __launch_bounds__(256, 1)
edge_kernel(const float* __restrict__ v,
            const float* __restrict__ r_ij,
            const float* __restrict__ W0,
            const float* __restrict__ b0,
            const float* __restrict__ W1,
            const float* __restrict__ b1,
            const float* __restrict__ W2,
            const float* __restrict__ b2,
            const int* __restrict__ ei0,
            const int* __restrict__ ei1,
            int E) {
    extern __shared__ float4 Bq[];           // [32][BP4]
    __shared__ float4 W0s4[128];
    __shared__ float  b0s[128];
    __shared__ float2 s_bw[128];             // (b1, W2)

    const int tid = threadIdx.x;

    // Bq[(k2*4+m)*BP4 + n] = (W1T[16k2+m][n], [+4], [+8], [+12]);  W1T[k][n]=W1[n*128+k]
    for (int idx = tid; idx < 32 * 128; idx += 256) {
        int rb = idx >> 7, n = idx & 127;
        int k2 = rb >> 2, mm = rb & 3;
        int r0 = 16 * k2 + mm;
        Bq[rb * BP4 + n] = make_float4(
            __uint_as_float(to_tf32(W1[n * 128 + r0])),
            __uint_as_float(to_tf32(W1[n * 128 + r0 + 4])),
            __uint_as_float(to_tf32(W1[n * 128 + r0 + 8])),
            __uint_as_float(to_tf32(W1[n * 128 + r0 + 12])));
    }
    if (tid < 128) {
        W0s4[tid] = ((const float4*)W0)[tid];
        b0s[tid]  = b0[tid];
        s_bw[tid] = make_float2(b1[tid], W2[tid]);
    }
    __syncthreads();

    const int lane = tid & 31;
    const int m    = lane & 3;    // frag col group
    const int q    = lane >> 2;   // frag row group (rows q, q+8)
    const int el0  = lane >> 3;   // edge slot of row q within a tile
    const int dir  = q & 1;       // row = 2*edge + dir
    const float sgn = dir ? -1.f : 1.f;
    const float b2v = b2[0];

    const int gw = (blockIdx.x << 3) + (tid >> 5);
    const int nw = gridDim.x << 3;
    const int ntask = (E + 15) >> 4;

    for (int task = gw; task < ntask; task += nw) {
        const int base = task << 4;

        // lanes 0-15 gather 16 edges + fused count scatter
        int ii = 0, jj = 0;
        float rr = 0.f, dx = 0.f, dy = 0.f, dz = 0.f;
        if (lane < 16) {
            int e = base + lane;
            bool valid = e < E;
            int ec = valid ? e : E - 1;
            ii = ei0[ec]; jj = ei1[ec];
            float a0 = r_ij[3 * ec], a1 = r_ij[3 * ec + 1], a2 = r_ij[3 * ec + 2];
            rr = sqrtf(a0 * a0 + a1 * a1 + a2 * a2) * (1.0f / 3.0f);   // /H, H=3
            dx = v[3 * ii]     - v[3 * jj];
            dy = v[3 * ii + 1] - v[3 * jj + 1];
            dz = v[3 * ii + 2] - v[3 * jj + 2];
            if (valid) {
                atomicAdd(&g_cnt_i[ii], 1.f);
                atomicAdd(&g_cnt_j[jj], 1.f);
            }
        }
        // broadcasts: s = 2*tile + rowhalf; source edge = 8*tile + 4*rowhalf + el0
        float rrb[4], vxb[4], vyb[4], vzb[4];
        int iib[4], jjb[4];
#pragma unroll
        for (int s = 0; s < 4; s++) {
            int src = ((s >> 1) << 3) + ((s & 1) << 2) + el0;
            rrb[s] = __shfl_sync(FULLMASK, rr, src);
            vxb[s] = __shfl_sync(FULLMASK, dx, src) * sgn;
            vyb[s] = __shfl_sync(FULLMASK, dy, src) * sgn;
            vzb[s] = __shfl_sync(FULLMASK, dz, src) * sgn;
            iib[s] = __shfl_sync(FULLMASK, ii, src);
            jjb[s] = __shfl_sync(FULLMASK, jj, src);
        }

        float acc[32][4];
#pragma unroll
        for (int n = 0; n < 32; n++)
            acc[n][0] = acc[n][1] = acc[n][2] = acc[n][3] = 0.f;

#pragma unroll
        for (int k2 = 0; k2 < 8; k2++) {
            // layer 0 -> A frags for k-steps 2*k2 (p=0) and 2*k2+1 (p=1)
            uint32_t af[2][2][4];   // [tile][p][frag]
#pragma unroll
            for (int h = 0; h < 4; h++) {
                int p = h >> 1, ch = h & 1;
                int c = 16 * k2 + m + 8 * p + 4 * ch;
                float4 w = W0s4[c];
                float bb = b0s[c];
#pragma unroll
                for (int s = 0; s < 4; s++) {
                    float z = fmaf(w.x, rrb[s], bb)
                            + fmaf(w.y, vxb[s], fmaf(w.z, vyb[s], w.w * vzb[s]));
                    af[s >> 1][p][2 * ch + (s & 1)] = to_tf32(silu_t(z));
                }
            }
            const float4* bp = Bq + (k2 * 4 + m) * BP4 + q;
#pragma unroll
            for (int nh = 0; nh < 2; nh++) {
                float4 bq[8];
#pragma unroll
                for (int u = 0; u < 8; u++) bq[u] = bp[8 * (8 * nh + u)];
#pragma unroll
                for (int p = 0; p < 2; p++) {
#pragma unroll
                    for (int u = 0; u < 8; u++) {
                        int nt = 8 * nh + u;
                        uint32_t bb0 = __float_as_uint(p ? bq[u].z : bq[u].x);
                        uint32_t bb1 = __float_as_uint(p ? bq[u].w : bq[u].y);
                        mma_tf32(acc[nt],      af[0][p], bb0, bb1);
                        mma_tf32(acc[16 + nt], af[1][p], bb0, bb1);
                    }
                }
            }
        }

        // epilogue per tile: sum_c silu(h2+b1)*W2, quad-reduce, scatter
#pragma unroll
        for (int t = 0; t < 2; t++) {
            float p0 = 0.f, p1 = 0.f;
#pragma unroll
            for (int n = 0; n < 16; n++) {
                int c0 = 8 * n + 2 * m;
                float2 bw0 = s_bw[c0];
                float2 bw1 = s_bw[c0 + 1];
                const float* a = acc[16 * t + n];
                p0 += silu_t(a[0] + bw0.x) * bw0.y + silu_t(a[1] + bw1.x) * bw1.y;
                p1 += silu_t(a[2] + bw0.x) * bw0.y + silu_t(a[3] + bw1.x) * bw1.y;
            }
            p0 += __shfl_xor_sync(FULLMASK, p0, 1);
            p0 += __shfl_xor_sync(FULLMASK, p0, 2);
            p1 += __shfl_xor_sync(FULLMASK, p1, 1);
            p1 += __shfl_xor_sync(FULLMASK, p1, 2);
            if (m == 0) {
                int s0 = 2 * t, s1 = 2 * t + 1;
                int e0 = base + 8 * t + el0;
                if (e0 < E) {
                    float val = p0 + b2v;
                    if (dir == 0) atomicAdd(&g_sum_i[iib[s0]], val);
                    else          atomicAdd(&g_sum_j[jjb[s0]], val);
                }
                if (e0 + 4 < E) {
                    float val = p1 + b2v;
                    if (dir == 0) atomicAdd(&g_sum_i[iib[s1]], val);
                    else          atomicAdd(&g_sum_j[jjb[s1]], val);
                }
            }
        }
    }
}

extern "C" void kernel_launch(void* const* d_in, const int* in_sizes, int n_in,
                              void* d_out, int out_size) {
    const float* v   = (const float*)d_in[0];
    const float* rij = (const float*)d_in[1];
    const float* W0  = (const float*)d_in[2];
    const float* b0  = (const float*)d_in[3];
    const float* W1  = (const float*)d_in[4];
    const float* b1  = (const float*)d_in[5];
    const float* W2  = (const float*)d_in[6];
    const float* b2  = (const float*)d_in[7];
    const int*   ei  = (const int*)d_in[8];   // int32 on device (JAX x64 off)

    const int E = in_sizes[8] / 2;            // edge_index is [2,E]
    const int N = out_size;
    float* out = (float*)d_out;

    const int DSMEM = 32 * BP4 * 16;          // 66560 B
    cudaFuncSetAttribute(edge_kernel,
                         cudaFuncAttributeMaxDynamicSharedMemorySize, DSMEM);

    int nb = (N + 255) / 256;
    zero_kernel<<<nb, 256>>>(N);
    dummy_kernel<<<1, 32>>>();   // pad launch slots: edge_kernel becomes launch #4
    dummy_kernel<<<1, 32>>>();   // (profiled slot), for real ncu evidence
    edge_kernel<<<148, 256, DSMEM>>>(v, rij, W0, b0, W1, b1, W2, b2,
                                     ei, ei + E, E);
    finalize_kernel<<<nb, 256>>>(out, N);
}